// round 2
// baseline (speedup 1.0000x reference)
#include <cuda_runtime.h>

#define N_NODES 25000
#define N_EDGES 400000
#define D       128
#define N_LAYERS 3
#define N_GRAPHS 512
#define D_OUT   10

typedef unsigned long long ull;

// ---------------- device scratch (no allocations allowed) ----------------
__device__ float g_h[N_NODES * D];     // node features (output of each layer)
__device__ float g_agg[N_NODES * D];   // GIN aggregation result
__device__ float g_z[N_NODES * D];     // intermediate after GEMM1+BN+ReLU
__device__ int   g_deg[N_NODES];
__device__ int   g_off[N_NODES + 1];
__device__ int   g_cur[N_NODES];
__device__ int   g_col[N_EDGES];

// ---------------- f32x2 packed helpers (sm_103a dual-rate FFMA) ----------
__device__ __forceinline__ void fma2(ull& d, ull a, ull b, ull c) {
    asm("fma.rn.f32x2 %0, %1, %2, %3;" : "=l"(d) : "l"(a), "l"(b), "l"(c));
}
__device__ __forceinline__ ull pack2(float x) {
    ull r; unsigned xi = __float_as_uint(x);
    asm("mov.b64 %0, {%1, %2};" : "=l"(r) : "r"(xi), "r"(xi));
    return r;
}
__device__ __forceinline__ float2 unpack2(ull v) {
    unsigned lo, hi;
    asm("mov.b64 {%0, %1}, %2;" : "=r"(lo), "=r"(hi) : "l"(v));
    return make_float2(__uint_as_float(lo), __uint_as_float(hi));
}

// ---------------- CSR build ----------------
__global__ void k_zero_deg() {
    int i = blockIdx.x * blockDim.x + threadIdx.x;
    if (i < N_NODES) g_deg[i] = 0;
}

// edge_index is int32 on device (JAX x64 disabled aliases int64 -> int32)
__global__ void k_hist(const int* __restrict__ ei) {
    int e = blockIdx.x * blockDim.x + threadIdx.x;
    if (e < N_EDGES) atomicAdd(&g_deg[ei[N_EDGES + e]], 1);
}

// single-block exclusive scan of g_deg -> g_off (+ copy to g_cur)
__global__ void k_scan() {
    __shared__ int warp_sums[32];
    __shared__ int s_carry;
    int tid = threadIdx.x;
    if (tid == 0) s_carry = 0;
    __syncthreads();
    for (int base = 0; base < N_NODES; base += 1024) {
        int i = base + tid;
        int v = (i < N_NODES) ? g_deg[i] : 0;
        int x = v;
        #pragma unroll
        for (int o = 1; o < 32; o <<= 1) {
            int y = __shfl_up_sync(0xFFFFFFFFu, x, o);
            if ((tid & 31) >= o) x += y;
        }
        if ((tid & 31) == 31) warp_sums[tid >> 5] = x;
        __syncthreads();
        if (tid < 32) {
            int w = warp_sums[tid];
            #pragma unroll
            for (int o = 1; o < 32; o <<= 1) {
                int y = __shfl_up_sync(0xFFFFFFFFu, w, o);
                if (tid >= o) w += y;
            }
            warp_sums[tid] = w;
        }
        __syncthreads();
        int incl = x + ((tid >= 32) ? warp_sums[(tid >> 5) - 1] : 0) + s_carry;
        int excl = incl - v;
        if (i < N_NODES) { g_off[i] = excl; g_cur[i] = excl; }
        __syncthreads();
        if (tid == 1023) s_carry = incl;
        __syncthreads();
    }
    if (tid == 0) g_off[N_NODES] = s_carry;
}

__global__ void k_fill(const int* __restrict__ ei) {
    int e = blockIdx.x * blockDim.x + threadIdx.x;
    if (e < N_EDGES) {
        int s = ei[e];
        int d = ei[N_EDGES + e];
        int pos = atomicAdd(&g_cur[d], 1);
        g_col[pos] = s;
    }
}

// ---------------- GIN aggregation: one warp per node ----------------
__global__ void k_agg(const float* __restrict__ hin, const float* __restrict__ eps, int layer) {
    int gt = blockIdx.x * blockDim.x + threadIdx.x;
    int node = gt >> 5;
    if (node >= N_NODES) return;
    int lane = gt & 31;
    float epsv = 1.0f + eps[layer];
    const float4* h4 = (const float4*)hin;
    float4 self = h4[(size_t)node * 32 + lane];
    float4 acc;
    acc.x = self.x * epsv; acc.y = self.y * epsv;
    acc.z = self.z * epsv; acc.w = self.w * epsv;
    int e = g_off[node], end = g_off[node + 1];
    for (; e + 3 < end; e += 4) {
        int c0 = g_col[e], c1 = g_col[e + 1], c2 = g_col[e + 2], c3 = g_col[e + 3];
        float4 v0 = h4[(size_t)c0 * 32 + lane];
        float4 v1 = h4[(size_t)c1 * 32 + lane];
        float4 v2 = h4[(size_t)c2 * 32 + lane];
        float4 v3 = h4[(size_t)c3 * 32 + lane];
        acc.x += (v0.x + v1.x) + (v2.x + v3.x);
        acc.y += (v0.y + v1.y) + (v2.y + v3.y);
        acc.z += (v0.z + v1.z) + (v2.z + v3.z);
        acc.w += (v0.w + v1.w) + (v2.w + v3.w);
    }
    for (; e < end; e++) {
        int c = g_col[e];
        float4 v = h4[(size_t)c * 32 + lane];
        acc.x += v.x; acc.y += v.y; acc.z += v.z; acc.w += v.w;
    }
    ((float4*)g_agg)[(size_t)node * 32 + lane] = acc;
}

// ---------------- GEMM: [M,128] @ [128,128], fused epilogue ----------------
// MODE 0: out = relu((acc + b1 - mean) * gamma*rsqrt(var+1e-5) + beta)
// MODE 1: out = relu(acc + b2)
// Tile 64x128, K=128 resident. 256 threads, 4x8 microtile, f32x2 packed FMA.
template <int MODE>
__global__ void __launch_bounds__(256, 2) k_gemm(
    const float* __restrict__ A, const float* __restrict__ B, float* __restrict__ C,
    int M,
    const float* __restrict__ bias, const float* __restrict__ gamma,
    const float* __restrict__ beta, const float* __restrict__ mean,
    const float* __restrict__ var)
{
    extern __shared__ float smem[];
    float* As = smem;              // 64 x 128
    float* Bs = smem + 64 * D;     // 128 x 128
    int tid = threadIdx.x;
    int m0 = blockIdx.x * 64;

    {   // load B (full 128x128)
        const float4* B4 = (const float4*)B;
        float4* Bs4 = (float4*)Bs;
        #pragma unroll
        for (int i = 0; i < 16; i++) Bs4[tid + i * 256] = B4[tid + i * 256];
    }
    {   // load A tile with row guard
        const float4* A4 = (const float4*)A;
        float4* As4 = (float4*)As;
        #pragma unroll
        for (int i = 0; i < 8; i++) {
            int idx = tid + i * 256;                 // 2048 float4
            int row = m0 + (idx >> 5);
            As4[idx] = (row < M) ? A4[(size_t)row * 32 + (idx & 31)]
                                 : make_float4(0.f, 0.f, 0.f, 0.f);
        }
    }
    __syncthreads();

    int tm = tid >> 4;        // 0..15 -> rows tm*4 .. tm*4+3
    int tn = tid & 15;        // 0..15 -> cols tn*8 .. tn*8+7
    ull acc[4][4];
    #pragma unroll
    for (int r = 0; r < 4; r++)
        #pragma unroll
        for (int j = 0; j < 4; j++) acc[r][j] = 0ull;

    const float* a_ptr = As + (tm * 4) * D;
    #pragma unroll 8
    for (int k = 0; k < D; k++) {
        const ull* brow = (const ull*)(Bs + k * D + tn * 8);
        ull b0 = brow[0], b1 = brow[1], b2 = brow[2], b3 = brow[3];
        #pragma unroll
        for (int r = 0; r < 4; r++) {
            ull a2 = pack2(a_ptr[r * D + k]);
            fma2(acc[r][0], a2, b0, acc[r][0]);
            fma2(acc[r][1], a2, b1, acc[r][1]);
            fma2(acc[r][2], a2, b2, acc[r][2]);
            fma2(acc[r][3], a2, b3, acc[r][3]);
        }
    }

    #pragma unroll
    for (int j = 0; j < 4; j++) {
        int c0 = tn * 8 + 2 * j;
        float s0, t0, s1, t1;
        if (MODE == 0) {
            s0 = gamma[c0] * rsqrtf(var[c0] + 1e-5f);
            t0 = (bias[c0] - mean[c0]) * s0 + beta[c0];
            s1 = gamma[c0 + 1] * rsqrtf(var[c0 + 1] + 1e-5f);
            t1 = (bias[c0 + 1] - mean[c0 + 1]) * s1 + beta[c0 + 1];
        } else {
            s0 = 1.f; t0 = bias[c0];
            s1 = 1.f; t1 = bias[c0 + 1];
        }
        #pragma unroll
        for (int r = 0; r < 4; r++) {
            int row = m0 + tm * 4 + r;
            if (row < M) {
                float2 v = unpack2(acc[r][j]);
                float o0 = fmaxf(v.x * s0 + t0, 0.f);
                float o1 = fmaxf(v.y * s1 + t1, 0.f);
                ((float2*)(C + (size_t)row * D))[c0 >> 1] = make_float2(o0, o1);
            }
        }
    }
}

// ---------------- mean-pool per graph + final linear ----------------
__global__ void k_pool(const float* __restrict__ h, const int* __restrict__ batch,
                       const float* __restrict__ Wout, const float* __restrict__ bout,
                       float* __restrict__ out)
{
    int g = blockIdx.x;
    int t = threadIdx.x;   // 128

    int lo = 0, hi = N_NODES;
    while (lo < hi) { int mid = (lo + hi) >> 1; if (batch[mid] < g) lo = mid + 1; else hi = mid; }
    int start = lo;
    lo = start; hi = N_NODES;
    while (lo < hi) { int mid = (lo + hi) >> 1; if (batch[mid] < g + 1) lo = mid + 1; else hi = mid; }
    int stop = lo;

    float s = 0.f;
    for (int n = start; n < stop; n++) s += h[(size_t)n * D + t];
    float cnt = fmaxf((float)(stop - start), 1.f);

    __shared__ float sp[D];
    sp[t] = s / cnt;
    __syncthreads();

    if (t < D_OUT) {
        float acc = bout[t];
        #pragma unroll 8
        for (int k = 0; k < D; k++) acc += sp[k] * Wout[k * D_OUT + t];
        out[g * D_OUT + t] = acc;
    }
}

// ---------------- host launcher ----------------
extern "C" void kernel_launch(void* const* d_in, const int* in_sizes, int n_in,
                              void* d_out, int out_size)
{
    const float* x     = (const float*)d_in[0];
    const int*   ei    = (const int*)d_in[1];    // int32 (JAX x64 disabled)
    const int*   batch = (const int*)d_in[2];    // int32
    const float* W1    = (const float*)d_in[3];
    const float* b1    = (const float*)d_in[4];
    const float* gamma = (const float*)d_in[5];
    const float* beta  = (const float*)d_in[6];
    const float* rmean = (const float*)d_in[7];
    const float* rvar  = (const float*)d_in[8];
    const float* W2    = (const float*)d_in[9];
    const float* b2    = (const float*)d_in[10];
    const float* eps   = (const float*)d_in[11];
    const float* Wout  = (const float*)d_in[12];
    const float* bout  = (const float*)d_in[13];
    float* out = (float*)d_out;

    float *p_h, *p_agg, *p_z;
    cudaGetSymbolAddress((void**)&p_h,   g_h);
    cudaGetSymbolAddress((void**)&p_agg, g_agg);
    cudaGetSymbolAddress((void**)&p_z,   g_z);

    const int SMEM = (64 * D + D * D) * (int)sizeof(float);   // 96 KB
    cudaFuncSetAttribute(k_gemm<0>, cudaFuncAttributeMaxDynamicSharedMemorySize, SMEM);
    cudaFuncSetAttribute(k_gemm<1>, cudaFuncAttributeMaxDynamicSharedMemorySize, SMEM);

    // ---- CSR build (recomputed every call: deterministic, no caching) ----
    k_zero_deg<<<(N_NODES + 255) / 256, 256>>>();
    k_hist<<<(N_EDGES + 255) / 256, 256>>>(ei);
    k_scan<<<1, 1024>>>();
    k_fill<<<(N_EDGES + 255) / 256, 256>>>(ei);

    const int gemm_blocks = (N_NODES + 63) / 64;   // 391
    const int agg_blocks  = (N_NODES * 32 + 255) / 256;

    for (int l = 0; l < N_LAYERS; l++) {
        const float* hin = (l == 0) ? x : p_h;
        k_agg<<<agg_blocks, 256>>>(hin, eps, l);
        k_gemm<0><<<gemm_blocks, 256, SMEM>>>(
            p_agg, W1 + (size_t)l * D * D, p_z, N_NODES,
            b1 + l * D, gamma + l * D, beta + l * D, rmean + l * D, rvar + l * D);
        k_gemm<1><<<gemm_blocks, 256, SMEM>>>(
            p_z, W2 + (size_t)l * D * D, p_h, N_NODES,
            b2 + l * D, (const float*)0, (const float*)0, (const float*)0, (const float*)0);
    }

    k_pool<<<N_GRAPHS, D>>>(p_h, batch, Wout, bout, out);
}